// round 5
// baseline (speedup 1.0000x reference)
#include <cuda_runtime.h>
#include <math.h>

#define BATCH   16384
#define D_INPUT 128
#define HIDDEN  2048
#define OUTP    54
#define NDIM    9
#define NBAS    5
#define NSTEP   100

// Scratch (device-global arrays: allocation is forbidden by harness rules)
__device__ float g_h1[(size_t)BATCH * HIDDEN];   // 128 MB
__device__ float g_h2[(size_t)BATCH * HIDDEN];   // 128 MB
__device__ float g_par[(size_t)BATCH * OUTP];    // 3.4 MB

// ---------------- f32x2 packed-FMA helpers (2x FFMA throughput on sm_103a) ----
__device__ __forceinline__ unsigned long long pack2(float x, float y) {
    unsigned long long r;
    asm("mov.b64 %0, {%1, %2};" : "=l"(r) : "f"(x), "f"(y));
    return r;
}
__device__ __forceinline__ void ffma2(unsigned long long &c,
                                      unsigned long long a,
                                      unsigned long long b) {
    asm("fma.rn.f32x2 %0, %1, %2, %0;" : "+l"(c) : "l"(a), "l"(b));
}
__device__ __forceinline__ float lo32(unsigned long long v) {
    return __uint_as_float((unsigned int)v);
}
__device__ __forceinline__ float hi32(unsigned long long v) {
    return __uint_as_float((unsigned int)(v >> 32));
}

// Accurate tanh (abs err ~1e-7), cheap: EX2 + RCP on MUFU pipe.
__device__ __forceinline__ float tanh_acc(float x) {
    float ax = fabsf(x);
    float t;
    if (ax > 9.0f) {
        t = 1.0f;
    } else {
        float e = __expf(2.0f * ax);
        t = 1.0f - __fdividef(2.0f, e + 1.0f);
    }
    return copysignf(t, x);
}

template <int MODE>
__device__ __forceinline__ float epilogue(float v) {
    if (MODE == 0) return tanh_acc(v);
    return v * 100.0f;   // MODE 1
}

// ---------------- 128x128x16 fp32 GEMM (NT: C[m,n] = sum_k A[m,k]*B[n,k]) ----
// 256 threads, 8x8 micro-tile per thread, inner loop = 32 FFMA2 + 8 packs + 4 LDS.128.
template <int MODE>
__global__ __launch_bounds__(256, 2)
void gemm128(const float* __restrict__ A, const float* __restrict__ Bm,
             const float* __restrict__ bias, float* __restrict__ C,
             int N, int K)
{
    __shared__ __align__(16) float As[16 * 128];
    __shared__ __align__(16) float Bs[16 * 128];

    const int tid = threadIdx.x;
    const int m0 = blockIdx.y * 128;
    const int n0 = blockIdx.x * 128;
    const int tr = tid >> 4;          // 0..15 (m direction)
    const int tc = tid & 15;          // 0..15 (n direction)

    const int r0 = tid >> 2;          // 0..63  (load row)
    const int r1 = r0 + 64;
    const int c0 = (tid & 3) << 2;    // 0,4,8,12 (load col group)

    unsigned long long acc[8][4];
#pragma unroll
    for (int i = 0; i < 8; i++)
#pragma unroll
        for (int j = 0; j < 4; j++) acc[i][j] = 0ull;

    for (int kt = 0; kt < K; kt += 16) {
        float4 va0 = *(const float4*)(A + (size_t)(m0 + r0) * K + kt + c0);
        float4 va1 = *(const float4*)(A + (size_t)(m0 + r1) * K + kt + c0);
        float4 vb0 = make_float4(0.f, 0.f, 0.f, 0.f);
        float4 vb1 = vb0;
        if (n0 + r0 < N) vb0 = *(const float4*)(Bm + (size_t)(n0 + r0) * K + kt + c0);
        if (n0 + r1 < N) vb1 = *(const float4*)(Bm + (size_t)(n0 + r1) * K + kt + c0);

        __syncthreads();   // previous tile fully consumed
        As[(c0 + 0) * 128 + r0] = va0.x; As[(c0 + 1) * 128 + r0] = va0.y;
        As[(c0 + 2) * 128 + r0] = va0.z; As[(c0 + 3) * 128 + r0] = va0.w;
        As[(c0 + 0) * 128 + r1] = va1.x; As[(c0 + 1) * 128 + r1] = va1.y;
        As[(c0 + 2) * 128 + r1] = va1.z; As[(c0 + 3) * 128 + r1] = va1.w;
        Bs[(c0 + 0) * 128 + r0] = vb0.x; Bs[(c0 + 1) * 128 + r0] = vb0.y;
        Bs[(c0 + 2) * 128 + r0] = vb0.z; Bs[(c0 + 3) * 128 + r0] = vb0.w;
        Bs[(c0 + 0) * 128 + r1] = vb1.x; Bs[(c0 + 1) * 128 + r1] = vb1.y;
        Bs[(c0 + 2) * 128 + r1] = vb1.z; Bs[(c0 + 3) * 128 + r1] = vb1.w;
        __syncthreads();

#pragma unroll
        for (int k = 0; k < 16; k++) {
            float4 al = *(const float4*)&As[k * 128 + tr * 4];
            float4 ah = *(const float4*)&As[k * 128 + tr * 4 + 64];
            ulonglong2 bl2 = *(const ulonglong2*)&Bs[k * 128 + tc * 4];
            ulonglong2 bh2 = *(const ulonglong2*)&Bs[k * 128 + tc * 4 + 64];
            unsigned long long b2[4] = {bl2.x, bl2.y, bh2.x, bh2.y};
            unsigned long long a2[8];
            a2[0] = pack2(al.x, al.x); a2[1] = pack2(al.y, al.y);
            a2[2] = pack2(al.z, al.z); a2[3] = pack2(al.w, al.w);
            a2[4] = pack2(ah.x, ah.x); a2[5] = pack2(ah.y, ah.y);
            a2[6] = pack2(ah.z, ah.z); a2[7] = pack2(ah.w, ah.w);
#pragma unroll
            for (int i = 0; i < 8; i++)
#pragma unroll
                for (int j = 0; j < 4; j++) ffma2(acc[i][j], a2[i], b2[j]);
        }
    }

#pragma unroll
    for (int i = 0; i < 8; i++) {
        int mg = m0 + ((i >> 2) << 6) + tr * 4 + (i & 3);
#pragma unroll
        for (int j = 0; j < 4; j++) {
            int ng = n0 + ((j >> 1) << 6) + ((j & 1) << 1) + tc * 4;
            float v0 = lo32(acc[i][j]);
            float v1 = hi32(acc[i][j]);
            if (ng < N)     C[(size_t)mg * N + ng]     = epilogue<MODE>(v0 + bias[ng]);
            if (ng + 1 < N) C[(size_t)mg * N + ng + 1] = epilogue<MODE>(v1 + bias[ng + 1]);
        }
    }
}

// ---------------- 64x64x16 variant for the thin final layer (N=54) -----------
__global__ __launch_bounds__(256, 4)
void gemm64(const float* __restrict__ A, const float* __restrict__ Bm,
            const float* __restrict__ bias, float* __restrict__ C,
            int N, int K)
{
    __shared__ __align__(16) float As[16 * 64];
    __shared__ __align__(16) float Bs[16 * 64];

    const int tid = threadIdx.x;
    const int m0 = blockIdx.y * 64;
    const int n0 = blockIdx.x * 64;
    const int tr = tid >> 4;          // 0..15 -> 4 rows each
    const int tc = tid & 15;          // 0..15 -> 4 cols each

    const int r = tid >> 2;           // 0..63
    const int c0 = (tid & 3) << 2;    // 0,4,8,12

    unsigned long long acc[4][2];
#pragma unroll
    for (int i = 0; i < 4; i++) { acc[i][0] = 0ull; acc[i][1] = 0ull; }

    for (int kt = 0; kt < K; kt += 16) {
        float4 va = *(const float4*)(A + (size_t)(m0 + r) * K + kt + c0);
        float4 vb = make_float4(0.f, 0.f, 0.f, 0.f);
        if (n0 + r < N) vb = *(const float4*)(Bm + (size_t)(n0 + r) * K + kt + c0);

        __syncthreads();
        As[(c0 + 0) * 64 + r] = va.x; As[(c0 + 1) * 64 + r] = va.y;
        As[(c0 + 2) * 64 + r] = va.z; As[(c0 + 3) * 64 + r] = va.w;
        Bs[(c0 + 0) * 64 + r] = vb.x; Bs[(c0 + 1) * 64 + r] = vb.y;
        Bs[(c0 + 2) * 64 + r] = vb.z; Bs[(c0 + 3) * 64 + r] = vb.w;
        __syncthreads();

#pragma unroll
        for (int k = 0; k < 16; k++) {
            float4 a = *(const float4*)&As[k * 64 + tr * 4];
            ulonglong2 bb = *(const ulonglong2*)&Bs[k * 64 + tc * 4];
            unsigned long long b2[2] = {bb.x, bb.y};
            unsigned long long a2[4];
            a2[0] = pack2(a.x, a.x); a2[1] = pack2(a.y, a.y);
            a2[2] = pack2(a.z, a.z); a2[3] = pack2(a.w, a.w);
#pragma unroll
            for (int i = 0; i < 4; i++) {
                ffma2(acc[i][0], a2[i], b2[0]);
                ffma2(acc[i][1], a2[i], b2[1]);
            }
        }
    }

#pragma unroll
    for (int i = 0; i < 4; i++) {
        int mg = m0 + tr * 4 + i;
#pragma unroll
        for (int j = 0; j < 2; j++) {
            int ng = n0 + tc * 4 + (j << 1);
            float v0 = lo32(acc[i][j]);
            float v1 = hi32(acc[i][j]);
            if (ng < N)     C[(size_t)mg * N + ng]     = (v0 + bias[ng]) * 100.0f;
            if (ng + 1 < N) C[(size_t)mg * N + ng + 1] = (v1 + bias[ng + 1]) * 100.0f;
        }
    }
}

// ---------------- DMP Euler integration ------------------------------------
// One thread per (batch, dof) row. Forcing coefficients coef[t][n] depend only
// on constants -> precomputed once per block in shared memory.
__global__ __launch_bounds__(256)
void dmp_kernel(const float* __restrict__ input, float* __restrict__ out)
{
    __shared__ float xs[NSTEP];
    __shared__ float coef[NSTEP][NBAS];

    const int tid = threadIdx.x;
    if (tid == 0) {
        float x = 1.0f;
        for (int i = 0; i < NSTEP; i++) {
            x = x - x * 0.01f;         // canonical system: x += (-A_X*x/TAU)*DT
            xs[i] = x;
        }
    }
    __syncthreads();
    if (tid < NSTEP) {
        float x = xs[tid];
        float p[NBAS];
        float s = 0.0f;
#pragma unroll
        for (int n = 0; n < NBAS; n++) {
            double cd = exp(-0.25 * (double)n);               // rbf centers (matches numpy f64->f32)
            float Cn = (float)cd;
            float Hn = (float)(11.180339887498949 / cd);      // 5^1.5 / c
            float d = x - Cn;
            p[n] = __expf(-Hn * d * d);
            s += p[n];
        }
        float inv = x / s;
#pragma unroll
        for (int n = 0; n < NBAS; n++) coef[tid][n] = p[n] * inv;
    }
    __syncthreads();

    int r = blockIdx.x * blockDim.x + tid;
    if (r >= BATCH * NDIM) return;
    int b = r / NDIM;
    int d = r - b * NDIM;

    const float* prm = g_par + (size_t)b * OUTP;
    float goal = prm[d];
    float w[NBAS];
#pragma unroll
    for (int n = 0; n < NBAS; n++) w[n] = prm[NDIM + d * NBAS + n];

    float y = input[(size_t)b * D_INPUT + 7 + d];    // state_index 7:16
    float z = input[(size_t)b * D_INPUT + 22 + d];   // vel_index 22:31 (z0 = dy0*TAU, TAU=1)
    float scale = goal - y;
    float prev = y;
    float* o = out + (size_t)r * 10;

#pragma unroll 1
    for (int kk = 0; kk < 10; kk++) {
#pragma unroll
        for (int i = 0; i < 10; i++) {
            int t = kk * 10 + i;
            float fx = scale * (w[0] * coef[t][0] + w[1] * coef[t][1] +
                                w[2] * coef[t][2] + w[3] * coef[t][3] +
                                w[4] * coef[t][4]);
            float dz = 25.0f * (6.25f * (goal - y) - z) + fx;   // old y, old z
            y = y + z * 0.01f;                                   // dy = old z
            z = z + dz * 0.01f;
        }
        o[kk] = y - prev;    // subsample every L_SUB=10, then diff
        prev = y;
    }
}

// GEMM wrappers that bind the device-global scratch directly (keeps
// kernel_launch free of any runtime API besides kernel launches).
__global__ void noop_kernel() {}

extern "C" void kernel_launch(void* const* d_in, const int* in_sizes, int n_in,
                              void* d_out, int out_size)
{
    const float* input = (const float*)d_in[0];
    const float* W0 = (const float*)d_in[1];
    const float* b0 = (const float*)d_in[2];
    const float* W1 = (const float*)d_in[3];
    const float* b1 = (const float*)d_in[4];
    const float* Wl = (const float*)d_in[5];
    const float* bl = (const float*)d_in[6];
    float* out = (float*)d_out;

    // Host-side addresses of __device__ globals: use the static mapping via
    // cudaGetSymbolAddress exactly once per process (cached in static locals;
    // deterministic, not a device allocation, not a stream operation).
    static float* h1 = nullptr;
    static float* h2 = nullptr;
    static float* par = nullptr;
    if (h1 == nullptr) {
        cudaGetSymbolAddress((void**)&h1, g_h1);
        cudaGetSymbolAddress((void**)&h2, g_h2);
        cudaGetSymbolAddress((void**)&par, g_par);
    }

    dim3 blk(256);
    // layer 0: (16384x128) @ (2048x128)^T -> tanh
    gemm128<0><<<dim3(HIDDEN / 128, BATCH / 128), blk>>>(input, W0, b0, h1, HIDDEN, D_INPUT);
    // layer 1: (16384x2048) @ (2048x2048)^T -> tanh   (dominant GEMM)
    gemm128<0><<<dim3(HIDDEN / 128, BATCH / 128), blk>>>(h1, W1, b1, h2, HIDDEN, HIDDEN);
    // final:   (16384x2048) @ (54x2048)^T -> *100
    gemm64<<<dim3(1, BATCH / 64), blk>>>(h2, Wl, bl, par, OUTP, HIDDEN);
    // DMP integration + subsample-diff
    dmp_kernel<<<(BATCH * NDIM + 255) / 256, blk>>>(input, out);
}

// round 11
// speedup vs baseline: 2.1851x; 2.1851x over previous
#include <cuda_runtime.h>
#include <cuda_bf16.h>
#include <math.h>
#include <stdint.h>

#define BATCH   16384
#define D_INPUT 128
#define HIDDEN  2048
#define OUTP    54
#define NDIM    9
#define NBAS    5
#define NSTEP   100

// ---------------- scratch (device globals: allocation forbidden) -------------
// 3K split layouts: A-side rows = [hi | hi | lo], B-side rows = [hi | lo | hi]
__device__ __nv_bfloat16 g_in3[(size_t)BATCH * 3 * D_INPUT];     // 12.6 MB
__device__ __nv_bfloat16 g_w0_3[(size_t)HIDDEN * 3 * D_INPUT];   // 1.6 MB
__device__ __nv_bfloat16 g_w1_3[(size_t)HIDDEN * 3 * HIDDEN];    // 25 MB
__device__ __nv_bfloat16 g_h1_3[(size_t)BATCH * 3 * HIDDEN];     // 201 MB
__device__ float g_h2[(size_t)BATCH * HIDDEN];                   // 128 MB
__device__ float g_par[(size_t)BATCH * OUTP];                    // 3.4 MB

// ---------------- helpers -----------------------------------------------------
__device__ __forceinline__ uint32_t smem_u32(const void* p) {
    uint32_t a;
    asm("{ .reg .u64 t; cvta.to.shared.u64 t, %1; cvt.u32.u64 %0, t; }" : "=r"(a) : "l"(p));
    return a;
}
#define SWZ128(off) ((off) ^ (((off) >> 3) & 0x70))

#define CP_ASYNC16(sm, gp) \
    asm volatile("cp.async.cg.shared.global [%0], [%1], 16;" :: "r"(sm), "l"(gp))
#define CP_COMMIT() asm volatile("cp.async.commit_group;" ::: "memory")
#define CP_WAIT(n)  asm volatile("cp.async.wait_group %0;" :: "n"(n) : "memory")

__device__ __forceinline__ void ldm4(uint32_t* r, uint32_t addr) {
    asm volatile("ldmatrix.sync.aligned.m8n8.x4.shared.b16 {%0,%1,%2,%3}, [%4];"
        : "=r"(r[0]), "=r"(r[1]), "=r"(r[2]), "=r"(r[3]) : "r"(addr));
}
__device__ __forceinline__ void mma16816(float* c, const uint32_t* a, const uint32_t* b) {
    asm volatile("mma.sync.aligned.m16n8k16.row.col.f32.bf16.bf16.f32 "
        "{%0,%1,%2,%3}, {%4,%5,%6,%7}, {%8,%9}, {%0,%1,%2,%3};"
        : "+f"(c[0]), "+f"(c[1]), "+f"(c[2]), "+f"(c[3])
        : "r"(a[0]), "r"(a[1]), "r"(a[2]), "r"(a[3]), "r"(b[0]), "r"(b[1]));
}

__device__ __forceinline__ float tanh_acc(float x) {
    float ax = fabsf(x);
    float t;
    if (ax > 9.0f) t = 1.0f;
    else {
        float e = __expf(2.0f * ax);
        t = 1.0f - __fdividef(2.0f, e + 1.0f);
    }
    return copysignf(t, x);
}

__device__ __forceinline__ unsigned long long pack2(float x, float y) {
    unsigned long long r;
    asm("mov.b64 %0, {%1, %2};" : "=l"(r) : "f"(x), "f"(y));
    return r;
}
__device__ __forceinline__ void ffma2(unsigned long long &c, unsigned long long a,
                                      unsigned long long b) {
    asm("fma.rn.f32x2 %0, %1, %2, %0;" : "+l"(c) : "l"(a), "l"(b));
}
__device__ __forceinline__ float lo32(unsigned long long v) { return __uint_as_float((unsigned)v); }
__device__ __forceinline__ float hi32(unsigned long long v) { return __uint_as_float((unsigned)(v >> 32)); }

// ---------------- fp32 -> [hi|hi|lo] / [hi|lo|hi] bf16 split ------------------
// ORDER 0 (A-side): row = [hi | hi | lo].  ORDER 1 (B-side): row = [hi | lo | hi].
template <int ORDER>
__global__ __launch_bounds__(256)
void split3(const float* __restrict__ src, __nv_bfloat16* __restrict__ dst,
            int K, int n4)
{
    int i = blockIdx.x * blockDim.x + threadIdx.x;
    if (i >= n4) return;
    int K4 = K >> 2;
    int row = i / K4, c4 = i - row * K4;
    float4 v = ((const float4*)src)[i];
    float f[4] = {v.x, v.y, v.z, v.w};
    ushort4 h, l;
    unsigned short* hp = &h.x;
    unsigned short* lp = &l.x;
#pragma unroll
    for (int j = 0; j < 4; j++) {
        __nv_bfloat16 hb = __float2bfloat16(f[j]);
        __nv_bfloat16 lb = __float2bfloat16(f[j] - __bfloat162float(hb));
        hp[j] = __bfloat16_as_ushort(hb);
        lp[j] = __bfloat16_as_ushort(lb);
    }
    __nv_bfloat16* base = dst + (size_t)row * 3 * K + c4 * 4;
    ((ushort4*)base)[0] = h;
    if (ORDER == 0) {
        ((ushort4*)(base + K))[0] = h;
        ((ushort4*)(base + 2 * K))[0] = l;
    } else {
        ((ushort4*)(base + K))[0] = l;
        ((ushort4*)(base + 2 * K))[0] = h;
    }
}

// ---------------- mma.sync bf16 GEMM (NT): C = tanh(A2 @ B2^T + bias) --------
// A2 [M][K2], B2 [N][K2] bf16 (3K split layouts). CTA 128x128, BK=64, 3-stage
// cp.async, 8 warps (2x4), warp tile 64x32, fp32 accum.
// MODE 0: write result as [hi|hi|lo] split-bf16 rows of width 3N (layer-0 h1).
// MODE 1: write fp32 (layer-1 h2).
#define MMA_STAGE_SZ 32768
#define MMA_SMEM     (3 * MMA_STAGE_SZ)

__device__ __forceinline__ void load_stage_mma(
    uint32_t sb, const __nv_bfloat16* __restrict__ A2,
    const __nv_bfloat16* __restrict__ B2,
    int m0, int n0, int kt, int K2, int tid)
{
#pragma unroll
    for (int i = 0; i < 4; i++) {
        int id = tid + i * 256;
        int row = id >> 3, c16 = id & 7;
        uint32_t sw = SWZ128((uint32_t)(row * 128 + c16 * 16));
        CP_ASYNC16(sb + sw,         A2 + (size_t)(m0 + row) * K2 + kt + c16 * 8);
        CP_ASYNC16(sb + 16384 + sw, B2 + (size_t)(n0 + row) * K2 + kt + c16 * 8);
    }
}

template <int MODE>
__global__ __launch_bounds__(256)
void gemm_mma(const __nv_bfloat16* __restrict__ A2, const __nv_bfloat16* __restrict__ B2,
              const float* __restrict__ bias, float* __restrict__ Cf,
              __nv_bfloat16* __restrict__ Csplit, int N, int K2)
{
    extern __shared__ char smem[];
    uint32_t sbase = smem_u32(smem);
    const int tid = threadIdx.x;
    const int wid = tid >> 5, lane = tid & 31;
    const int m0 = blockIdx.y * 128;
    const int n0 = blockIdx.x * 128;
    const int wm = wid >> 2, wn = wid & 3;
    const int nc = K2 / 64;

    // lane-dependent in-tile byte offsets (pre-swizzle)
    uint32_t roA[4], roB[2];
#pragma unroll
    for (int mt = 0; mt < 4; mt++)
        roA[mt] = (uint32_t)((wm * 64 + mt * 16 + (lane & 15)) * 128 + (lane >> 4) * 16);
#pragma unroll
    for (int p = 0; p < 2; p++)
        roB[p] = (uint32_t)((wn * 32 + p * 16 + (lane & 7) + ((lane >> 4) << 3)) * 128 +
                            ((lane >> 3) & 1) * 16);

    float acc[4][4][4];
#pragma unroll
    for (int a = 0; a < 4; a++)
#pragma unroll
        for (int b = 0; b < 4; b++)
#pragma unroll
            for (int q = 0; q < 4; q++) acc[a][b][q] = 0.0f;

    load_stage_mma(sbase, A2, B2, m0, n0, 0, K2, tid);
    CP_COMMIT();
    load_stage_mma(sbase + MMA_STAGE_SZ, A2, B2, m0, n0, 64, K2, tid);
    CP_COMMIT();

    for (int c = 0; c < nc; c++) {
        if (c + 2 < nc)
            load_stage_mma(sbase + ((c + 2) % 3) * MMA_STAGE_SZ, A2, B2, m0, n0,
                           (c + 2) * 64, K2, tid);
        CP_COMMIT();           // empty group when no load: keeps wait_group count valid
        CP_WAIT(2);            // chunk c resident
        __syncthreads();

        uint32_t sA = sbase + (c % 3) * MMA_STAGE_SZ;
        uint32_t sB = sA + 16384;
#pragma unroll
        for (int ks = 0; ks < 4; ks++) {
            uint32_t af[4][4], bf[2][4];
#pragma unroll
            for (int mt = 0; mt < 4; mt++)
                ldm4(af[mt], sA + SWZ128(roA[mt] + ks * 32));
#pragma unroll
            for (int p = 0; p < 2; p++)
                ldm4(bf[p], sB + SWZ128(roB[p] + ks * 32));
#pragma unroll
            for (int mt = 0; mt < 4; mt++)
#pragma unroll
                for (int nt = 0; nt < 4; nt++)
                    mma16816(acc[mt][nt], af[mt], &bf[nt >> 1][(nt & 1) * 2]);
        }
        __syncthreads();       // all warps done with stage c before it is reloaded
    }

    // epilogue (register accumulators -> gmem)
    const int mrow = m0 + wm * 64 + (lane >> 2);
    const int nbase = n0 + wn * 32 + 2 * (lane & 3);
#pragma unroll
    for (int mt = 0; mt < 4; mt++) {
#pragma unroll
        for (int nt = 0; nt < 4; nt++) {
            int n = nbase + nt * 8;
            float2 b2 = *(const float2*)(bias + n);
            float v0 = tanh_acc(acc[mt][nt][0] + b2.x);
            float v1 = tanh_acc(acc[mt][nt][1] + b2.y);
            float v2 = tanh_acc(acc[mt][nt][2] + b2.x);
            float v3 = tanh_acc(acc[mt][nt][3] + b2.y);
            int r0 = mrow + mt * 16, r1 = r0 + 8;
            if (MODE == 0) {
                // split-store into [hi|hi|lo] rows of width 3N
#pragma unroll
                for (int h = 0; h < 2; h++) {
                    float u0 = h ? v2 : v0, u1 = h ? v3 : v1;
                    int r = h ? r1 : r0;
                    __nv_bfloat16 h0 = __float2bfloat16(u0);
                    __nv_bfloat16 h1 = __float2bfloat16(u1);
                    __nv_bfloat16 l0 = __float2bfloat16(u0 - __bfloat162float(h0));
                    __nv_bfloat16 l1 = __float2bfloat16(u1 - __bfloat162float(h1));
                    uint32_t hp = (uint32_t)__bfloat16_as_ushort(h0) |
                                  ((uint32_t)__bfloat16_as_ushort(h1) << 16);
                    uint32_t lp = (uint32_t)__bfloat16_as_ushort(l0) |
                                  ((uint32_t)__bfloat16_as_ushort(l1) << 16);
                    __nv_bfloat16* row = Csplit + (size_t)r * 3 * N + n;
                    *(uint32_t*)row = hp;
                    *(uint32_t*)(row + N) = hp;
                    *(uint32_t*)(row + 2 * N) = lp;
                }
            } else {
                *(float2*)(Cf + (size_t)r0 * N + n) = make_float2(v0, v1);
                *(float2*)(Cf + (size_t)r1 * N + n) = make_float2(v2, v3);
            }
        }
    }
}

// ---------------- 64x64x16 SIMT FFMA2 GEMM for thin final layer (N=54) -------
__global__ __launch_bounds__(256, 4)
void gemm64(const float* __restrict__ A, const float* __restrict__ Bm,
            const float* __restrict__ bias, float* __restrict__ C,
            int N, int K)
{
    __shared__ __align__(16) float As[16 * 64];
    __shared__ __align__(16) float Bs[16 * 64];

    const int tid = threadIdx.x;
    const int m0 = blockIdx.y * 64;
    const int n0 = blockIdx.x * 64;
    const int tr = tid >> 4;
    const int tc = tid & 15;
    const int r = tid >> 2;
    const int c0 = (tid & 3) << 2;

    unsigned long long acc[4][2];
#pragma unroll
    for (int i = 0; i < 4; i++) { acc[i][0] = 0ull; acc[i][1] = 0ull; }

    for (int kt = 0; kt < K; kt += 16) {
        float4 va = *(const float4*)(A + (size_t)(m0 + r) * K + kt + c0);
        float4 vb = make_float4(0.f, 0.f, 0.f, 0.f);
        if (n0 + r < N) vb = *(const float4*)(Bm + (size_t)(n0 + r) * K + kt + c0);

        __syncthreads();
        As[(c0 + 0) * 64 + r] = va.x; As[(c0 + 1) * 64 + r] = va.y;
        As[(c0 + 2) * 64 + r] = va.z; As[(c0 + 3) * 64 + r] = va.w;
        Bs[(c0 + 0) * 64 + r] = vb.x; Bs[(c0 + 1) * 64 + r] = vb.y;
        Bs[(c0 + 2) * 64 + r] = vb.z; Bs[(c0 + 3) * 64 + r] = vb.w;
        __syncthreads();

#pragma unroll
        for (int k = 0; k < 16; k++) {
            float4 a = *(const float4*)&As[k * 64 + tr * 4];
            ulonglong2 bb = *(const ulonglong2*)&Bs[k * 64 + tc * 4];
            unsigned long long b2[2] = {bb.x, bb.y};
            unsigned long long a2[4];
            a2[0] = pack2(a.x, a.x); a2[1] = pack2(a.y, a.y);
            a2[2] = pack2(a.z, a.z); a2[3] = pack2(a.w, a.w);
#pragma unroll
            for (int i = 0; i < 4; i++) {
                ffma2(acc[i][0], a2[i], b2[0]);
                ffma2(acc[i][1], a2[i], b2[1]);
            }
        }
    }

#pragma unroll
    for (int i = 0; i < 4; i++) {
        int mg = m0 + tr * 4 + i;
#pragma unroll
        for (int j = 0; j < 2; j++) {
            int ng = n0 + tc * 4 + (j << 1);
            float v0 = lo32(acc[i][j]);
            float v1 = hi32(acc[i][j]);
            if (ng < N)     C[(size_t)mg * N + ng]     = (v0 + bias[ng]) * 100.0f;
            if (ng + 1 < N) C[(size_t)mg * N + ng + 1] = (v1 + bias[ng + 1]) * 100.0f;
        }
    }
}

// ---------------- DMP Euler integration --------------------------------------
__global__ __launch_bounds__(256)
void dmp_kernel(const float* __restrict__ input, float* __restrict__ out)
{
    __shared__ float xs[NSTEP];
    __shared__ float coef[NSTEP][NBAS];

    const int tid = threadIdx.x;
    if (tid == 0) {
        float x = 1.0f;
        for (int i = 0; i < NSTEP; i++) { x = x - x * 0.01f; xs[i] = x; }
    }
    __syncthreads();
    if (tid < NSTEP) {
        float x = xs[tid];
        float p[NBAS];
        float s = 0.0f;
#pragma unroll
        for (int n = 0; n < NBAS; n++) {
            double cd = exp(-0.25 * (double)n);
            float Cn = (float)cd;
            float Hn = (float)(11.180339887498949 / cd);
            float d = x - Cn;
            p[n] = __expf(-Hn * d * d);
            s += p[n];
        }
        float inv = x / s;
#pragma unroll
        for (int n = 0; n < NBAS; n++) coef[tid][n] = p[n] * inv;
    }
    __syncthreads();

    int r = blockIdx.x * blockDim.x + tid;
    if (r >= BATCH * NDIM) return;
    int b = r / NDIM;
    int d = r - b * NDIM;

    const float* prm = g_par + (size_t)b * OUTP;
    float goal = prm[d];
    float w[NBAS];
#pragma unroll
    for (int n = 0; n < NBAS; n++) w[n] = prm[NDIM + d * NBAS + n];

    float y = input[(size_t)b * D_INPUT + 7 + d];
    float z = input[(size_t)b * D_INPUT + 22 + d];
    float scale = goal - y;
    float prev = y;
    float* o = out + (size_t)r * 10;

#pragma unroll 1
    for (int kk = 0; kk < 10; kk++) {
#pragma unroll
        for (int i = 0; i < 10; i++) {
            int t = kk * 10 + i;
            float fx = scale * (w[0] * coef[t][0] + w[1] * coef[t][1] +
                                w[2] * coef[t][2] + w[3] * coef[t][3] +
                                w[4] * coef[t][4]);
            float dz = 25.0f * (6.25f * (goal - y) - z) + fx;
            y = y + z * 0.01f;
            z = z + dz * 0.01f;
        }
        o[kk] = y - prev;
        prev = y;
    }
}

// ---------------- launch ------------------------------------------------------
extern "C" void kernel_launch(void* const* d_in, const int* in_sizes, int n_in,
                              void* d_out, int out_size)
{
    const float* input = (const float*)d_in[0];
    const float* W0 = (const float*)d_in[1];
    const float* b0 = (const float*)d_in[2];
    const float* W1 = (const float*)d_in[3];
    const float* b1 = (const float*)d_in[4];
    const float* Wl = (const float*)d_in[5];
    const float* bl = (const float*)d_in[6];
    float* out = (float*)d_out;

    static __nv_bfloat16 *in3, *w0_3, *w1_3, *h1_3;
    static float *h2, *par;
    static bool init_done = false;
    if (!init_done) {
        cudaGetSymbolAddress((void**)&in3, g_in3);
        cudaGetSymbolAddress((void**)&w0_3, g_w0_3);
        cudaGetSymbolAddress((void**)&w1_3, g_w1_3);
        cudaGetSymbolAddress((void**)&h1_3, g_h1_3);
        cudaGetSymbolAddress((void**)&h2, g_h2);
        cudaGetSymbolAddress((void**)&par, g_par);
        cudaFuncSetAttribute(gemm_mma<0>, cudaFuncAttributeMaxDynamicSharedMemorySize, MMA_SMEM);
        cudaFuncSetAttribute(gemm_mma<1>, cudaFuncAttributeMaxDynamicSharedMemorySize, MMA_SMEM);
        init_done = true;
    }

    dim3 blk(256);
    // fp32 -> 3K split-bf16 layouts
    split3<0><<<(BATCH * D_INPUT / 4 + 255) / 256, blk>>>(input, in3, D_INPUT, BATCH * D_INPUT / 4);
    split3<1><<<(HIDDEN * D_INPUT / 4 + 255) / 256, blk>>>(W0, w0_3, D_INPUT, HIDDEN * D_INPUT / 4);
    split3<1><<<(HIDDEN * HIDDEN / 4 + 255) / 256, blk>>>(W1, w1_3, HIDDEN, HIDDEN * HIDDEN / 4);

    // layer 0: tanh(input @ W0^T + b0) -> h1 in [hi|hi|lo] layout (K2 = 384)
    gemm_mma<0><<<dim3(HIDDEN / 128, BATCH / 128), blk, MMA_SMEM>>>(
        in3, w0_3, b0, nullptr, h1_3, HIDDEN, 3 * D_INPUT);
    // layer 1: tanh(h1 @ W1^T + b1) -> fp32 h2 (K2 = 6144, dominant)
    gemm_mma<1><<<dim3(HIDDEN / 128, BATCH / 128), blk, MMA_SMEM>>>(
        h1_3, w1_3, b1, h2, nullptr, HIDDEN, 3 * HIDDEN);
    // final: (h2 @ Wl^T + bl) * 100
    gemm64<<<dim3(1, BATCH / 64), blk>>>(h2, Wl, bl, par, OUTP, HIDDEN);
    // DMP integration + subsample-diff
    dmp_kernel<<<(BATCH * NDIM + 255) / 256, blk>>>(input, out);
}

// round 12
// speedup vs baseline: 2.2133x; 1.0129x over previous
#include <cuda_runtime.h>
#include <cuda_bf16.h>
#include <math.h>
#include <stdint.h>

#define BATCH   16384
#define D_INPUT 128
#define HIDDEN  2048
#define OUTP    54
#define NDIM    9
#define NBAS    5
#define NSTEP   100

// ---------------- scratch (device globals: allocation forbidden) -------------
// 3K split layouts: A-side rows = [hi | hi | lo], B-side rows = [hi | lo | hi]
__device__ __nv_bfloat16 g_in3[(size_t)BATCH * 3 * D_INPUT];     // 12.6 MB
__device__ __nv_bfloat16 g_w0_3[(size_t)HIDDEN * 3 * D_INPUT];   // 1.6 MB
__device__ __nv_bfloat16 g_w1_3[(size_t)HIDDEN * 3 * HIDDEN];    // 25 MB
__device__ __nv_bfloat16 g_h1_3[(size_t)BATCH * 3 * HIDDEN];     // 201 MB
__device__ float g_h2[(size_t)BATCH * HIDDEN];                   // 128 MB
__device__ float g_par[(size_t)BATCH * OUTP];                    // 3.4 MB

// ---------------- helpers -----------------------------------------------------
__device__ __forceinline__ uint32_t smem_u32(const void* p) {
    uint32_t a;
    asm("{ .reg .u64 t; cvta.to.shared.u64 t, %1; cvt.u32.u64 %0, t; }" : "=r"(a) : "l"(p));
    return a;
}
#define SWZ128(off) ((off) ^ (((off) >> 3) & 0x70))

#define CP_ASYNC16(sm, gp) \
    asm volatile("cp.async.cg.shared.global [%0], [%1], 16;" :: "r"(sm), "l"(gp))
#define CP_COMMIT() asm volatile("cp.async.commit_group;" ::: "memory")
#define CP_WAIT(n)  asm volatile("cp.async.wait_group %0;" :: "n"(n) : "memory")

__device__ __forceinline__ void ldm4(uint32_t* r, uint32_t addr) {
    asm volatile("ldmatrix.sync.aligned.m8n8.x4.shared.b16 {%0,%1,%2,%3}, [%4];"
        : "=r"(r[0]), "=r"(r[1]), "=r"(r[2]), "=r"(r[3]) : "r"(addr));
}
__device__ __forceinline__ void mma16816(float* c, const uint32_t* a, const uint32_t* b) {
    asm volatile("mma.sync.aligned.m16n8k16.row.col.f32.bf16.bf16.f32 "
        "{%0,%1,%2,%3}, {%4,%5,%6,%7}, {%8,%9}, {%0,%1,%2,%3};"
        : "+f"(c[0]), "+f"(c[1]), "+f"(c[2]), "+f"(c[3])
        : "r"(a[0]), "r"(a[1]), "r"(a[2]), "r"(a[3]), "r"(b[0]), "r"(b[1]));
}

__device__ __forceinline__ float tanh_acc(float x) {
    float ax = fabsf(x);
    float t;
    if (ax > 9.0f) t = 1.0f;
    else {
        float e = __expf(2.0f * ax);
        t = 1.0f - __fdividef(2.0f, e + 1.0f);
    }
    return copysignf(t, x);
}

__device__ __forceinline__ unsigned long long pack2(float x, float y) {
    unsigned long long r;
    asm("mov.b64 %0, {%1, %2};" : "=l"(r) : "f"(x), "f"(y));
    return r;
}
__device__ __forceinline__ void ffma2(unsigned long long &c, unsigned long long a,
                                      unsigned long long b) {
    asm("fma.rn.f32x2 %0, %1, %2, %0;" : "+l"(c) : "l"(a), "l"(b));
}
__device__ __forceinline__ float lo32(unsigned long long v) { return __uint_as_float((unsigned)v); }
__device__ __forceinline__ float hi32(unsigned long long v) { return __uint_as_float((unsigned)(v >> 32)); }

// ---------------- fp32 -> [hi|hi|lo] / [hi|lo|hi] bf16 split ------------------
template <int ORDER>
__global__ __launch_bounds__(256)
void split3(const float* __restrict__ src, __nv_bfloat16* __restrict__ dst,
            int K, int n4)
{
    int i = blockIdx.x * blockDim.x + threadIdx.x;
    if (i >= n4) return;
    int K4 = K >> 2;
    int row = i / K4, c4 = i - row * K4;
    float4 v = ((const float4*)src)[i];
    float f[4] = {v.x, v.y, v.z, v.w};
    ushort4 h, l;
    unsigned short* hp = &h.x;
    unsigned short* lp = &l.x;
#pragma unroll
    for (int j = 0; j < 4; j++) {
        __nv_bfloat16 hb = __float2bfloat16(f[j]);
        __nv_bfloat16 lb = __float2bfloat16(f[j] - __bfloat162float(hb));
        hp[j] = __bfloat16_as_ushort(hb);
        lp[j] = __bfloat16_as_ushort(lb);
    }
    __nv_bfloat16* base = dst + (size_t)row * 3 * K + c4 * 4;
    ((ushort4*)base)[0] = h;
    if (ORDER == 0) {
        ((ushort4*)(base + K))[0] = h;
        ((ushort4*)(base + 2 * K))[0] = l;
    } else {
        ((ushort4*)(base + K))[0] = l;
        ((ushort4*)(base + 2 * K))[0] = h;
    }
}

// ---------------- mma.sync bf16 GEMM (NT): C = tanh(A2 @ B2^T + bias) --------
// CTA tile 256x128, BK=64, 512 threads (4x4 warps, warp tile 64x32), 3-stage
// cp.async pipeline with ONE barrier per chunk, LDSM/MMA interleaved.
// MODE 0: write result as [hi|hi|lo] split-bf16 rows of width 3N (layer-0 h1).
// MODE 1: write fp32 (layer-1 h2).
#define MMA_STAGE_SZ 49152            // A 32KB + B 16KB
#define MMA_B_OFF    32768
#define MMA_SMEM     (3 * MMA_STAGE_SZ)

__device__ __forceinline__ void load_stage_mma(
    uint32_t sb, const __nv_bfloat16* __restrict__ A2,
    const __nv_bfloat16* __restrict__ B2,
    int m0, int n0, int kt, int K2, int tid)
{
    // A: 256 rows x 8 x 16B
#pragma unroll
    for (int i = 0; i < 4; i++) {
        int id = tid + i * 512;
        int row = id >> 3, c16 = id & 7;
        uint32_t sw = SWZ128((uint32_t)(row * 128 + c16 * 16));
        CP_ASYNC16(sb + sw, A2 + (size_t)(m0 + row) * K2 + kt + c16 * 8);
    }
    // B: 128 rows x 8 x 16B
#pragma unroll
    for (int i = 0; i < 2; i++) {
        int id = tid + i * 512;
        int row = id >> 3, c16 = id & 7;
        uint32_t sw = SWZ128((uint32_t)(row * 128 + c16 * 16));
        CP_ASYNC16(sb + MMA_B_OFF + sw, B2 + (size_t)(n0 + row) * K2 + kt + c16 * 8);
    }
}

template <int MODE>
__global__ __launch_bounds__(512, 1)
void gemm_mma(const __nv_bfloat16* __restrict__ A2, const __nv_bfloat16* __restrict__ B2,
              const float* __restrict__ bias, float* __restrict__ Cf,
              __nv_bfloat16* __restrict__ Csplit, int N, int K2)
{
    extern __shared__ char smem[];
    uint32_t sbase = smem_u32(smem);
    const int tid = threadIdx.x;
    const int wid = tid >> 5, lane = tid & 31;
    const int m0 = blockIdx.y * 256;
    const int n0 = blockIdx.x * 128;
    const int wm = wid >> 2, wn = wid & 3;     // 4x4 warp grid
    const int nc = K2 / 64;

    // in-tile byte offsets (pre-swizzle), region-relative
    uint32_t roA[4], roB[2];
#pragma unroll
    for (int mt = 0; mt < 4; mt++)
        roA[mt] = (uint32_t)((wm * 64 + mt * 16 + (lane & 15)) * 128 + (lane >> 4) * 16);
#pragma unroll
    for (int p = 0; p < 2; p++)
        roB[p] = (uint32_t)((wn * 32 + p * 16 + (lane & 7) + ((lane >> 4) << 3)) * 128 +
                            ((lane >> 3) & 1) * 16);

    float acc[4][4][4];
#pragma unroll
    for (int a = 0; a < 4; a++)
#pragma unroll
        for (int b = 0; b < 4; b++)
#pragma unroll
            for (int q = 0; q < 4; q++) acc[a][b][q] = 0.0f;

    load_stage_mma(sbase, A2, B2, m0, n0, 0, K2, tid);
    CP_COMMIT();
    load_stage_mma(sbase + MMA_STAGE_SZ, A2, B2, m0, n0, 64, K2, tid);
    CP_COMMIT();

    for (int c = 0; c < nc; c++) {
        CP_WAIT(1);            // stage c resident (stage c+1 may still be in flight)
        __syncthreads();       // all warps past compute of c-1; slot (c-1)%3 free

        uint32_t sA = sbase + (c % 3) * MMA_STAGE_SZ;
        uint32_t sB = sA + MMA_B_OFF;

        uint32_t af[4][4], bf[2][2][4];
        // preload k-step 0
#pragma unroll
        for (int mt = 0; mt < 4; mt++) ldm4(af[mt], sA + SWZ128(roA[mt]));
#pragma unroll
        for (int p = 0; p < 2; p++) ldm4(bf[0][p], sB + SWZ128(roB[p]));

#pragma unroll
        for (int ks = 0; ks < 4; ks++) {
            const int cur = ks & 1, nxt = cur ^ 1;
            if (ks < 3) {      // B fragments for next k-step (double buffer)
#pragma unroll
                for (int p = 0; p < 2; p++)
                    ldm4(bf[nxt][p], sB + SWZ128(roB[p] + (ks + 1) * 32));
            }
#pragma unroll
            for (int mt = 0; mt < 4; mt++) {
#pragma unroll
                for (int nt = 0; nt < 4; nt++)
                    mma16816(acc[mt][nt], af[mt], &bf[cur][nt >> 1][(nt & 1) * 2]);
                if (ks < 3)    // reload A[mt] for next k-step right after last use
                    ldm4(af[mt], sA + SWZ128(roA[mt] + (ks + 1) * 32));
            }
        }

        // prefetch stage c+2 (slot (c-1)%3 — free since the barrier above)
        if (c + 2 < nc)
            load_stage_mma(sbase + ((c + 2) % 3) * MMA_STAGE_SZ, A2, B2, m0, n0,
                           (c + 2) * 64, K2, tid);
        CP_COMMIT();           // commit every iteration (empty group ok)
    }

    // epilogue (register accumulators -> gmem)
    const int mrow = m0 + wm * 64 + (lane >> 2);
    const int nbase = n0 + wn * 32 + 2 * (lane & 3);
#pragma unroll
    for (int mt = 0; mt < 4; mt++) {
#pragma unroll
        for (int nt = 0; nt < 4; nt++) {
            int n = nbase + nt * 8;
            float2 b2 = *(const float2*)(bias + n);
            float v0 = tanh_acc(acc[mt][nt][0] + b2.x);
            float v1 = tanh_acc(acc[mt][nt][1] + b2.y);
            float v2 = tanh_acc(acc[mt][nt][2] + b2.x);
            float v3 = tanh_acc(acc[mt][nt][3] + b2.y);
            int r0 = mrow + mt * 16, r1 = r0 + 8;
            if (MODE == 0) {
#pragma unroll
                for (int h = 0; h < 2; h++) {
                    float u0 = h ? v2 : v0, u1 = h ? v3 : v1;
                    int r = h ? r1 : r0;
                    __nv_bfloat16 h0 = __float2bfloat16(u0);
                    __nv_bfloat16 h1 = __float2bfloat16(u1);
                    __nv_bfloat16 l0 = __float2bfloat16(u0 - __bfloat162float(h0));
                    __nv_bfloat16 l1 = __float2bfloat16(u1 - __bfloat162float(h1));
                    uint32_t hp = (uint32_t)__bfloat16_as_ushort(h0) |
                                  ((uint32_t)__bfloat16_as_ushort(h1) << 16);
                    uint32_t lp = (uint32_t)__bfloat16_as_ushort(l0) |
                                  ((uint32_t)__bfloat16_as_ushort(l1) << 16);
                    __nv_bfloat16* row = Csplit + (size_t)r * 3 * N + n;
                    *(uint32_t*)row = hp;
                    *(uint32_t*)(row + N) = hp;
                    *(uint32_t*)(row + 2 * N) = lp;
                }
            } else {
                *(float2*)(Cf + (size_t)r0 * N + n) = make_float2(v0, v1);
                *(float2*)(Cf + (size_t)r1 * N + n) = make_float2(v2, v3);
            }
        }
    }
}

// ---------------- 64x64x16 SIMT FFMA2 GEMM for thin final layer (N=54) -------
__global__ __launch_bounds__(256, 4)
void gemm64(const float* __restrict__ A, const float* __restrict__ Bm,
            const float* __restrict__ bias, float* __restrict__ C,
            int N, int K)
{
    __shared__ __align__(16) float As[16 * 64];
    __shared__ __align__(16) float Bs[16 * 64];

    const int tid = threadIdx.x;
    const int m0 = blockIdx.y * 64;
    const int n0 = blockIdx.x * 64;
    const int tr = tid >> 4;
    const int tc = tid & 15;
    const int r = tid >> 2;
    const int c0 = (tid & 3) << 2;

    unsigned long long acc[4][2];
#pragma unroll
    for (int i = 0; i < 4; i++) { acc[i][0] = 0ull; acc[i][1] = 0ull; }

    for (int kt = 0; kt < K; kt += 16) {
        float4 va = *(const float4*)(A + (size_t)(m0 + r) * K + kt + c0);
        float4 vb = make_float4(0.f, 0.f, 0.f, 0.f);
        if (n0 + r < N) vb = *(const float4*)(Bm + (size_t)(n0 + r) * K + kt + c0);

        __syncthreads();
        As[(c0 + 0) * 64 + r] = va.x; As[(c0 + 1) * 64 + r] = va.y;
        As[(c0 + 2) * 64 + r] = va.z; As[(c0 + 3) * 64 + r] = va.w;
        Bs[(c0 + 0) * 64 + r] = vb.x; Bs[(c0 + 1) * 64 + r] = vb.y;
        Bs[(c0 + 2) * 64 + r] = vb.z; Bs[(c0 + 3) * 64 + r] = vb.w;
        __syncthreads();

#pragma unroll
        for (int k = 0; k < 16; k++) {
            float4 a = *(const float4*)&As[k * 64 + tr * 4];
            ulonglong2 bb = *(const ulonglong2*)&Bs[k * 64 + tc * 4];
            unsigned long long b2[2] = {bb.x, bb.y};
            unsigned long long a2[4];
            a2[0] = pack2(a.x, a.x); a2[1] = pack2(a.y, a.y);
            a2[2] = pack2(a.z, a.z); a2[3] = pack2(a.w, a.w);
#pragma unroll
            for (int i = 0; i < 4; i++) {
                ffma2(acc[i][0], a2[i], b2[0]);
                ffma2(acc[i][1], a2[i], b2[1]);
            }
        }
    }

#pragma unroll
    for (int i = 0; i < 4; i++) {
        int mg = m0 + tr * 4 + i;
#pragma unroll
        for (int j = 0; j < 2; j++) {
            int ng = n0 + tc * 4 + (j << 1);
            float v0 = lo32(acc[i][j]);
            float v1 = hi32(acc[i][j]);
            if (ng < N)     C[(size_t)mg * N + ng]     = (v0 + bias[ng]) * 100.0f;
            if (ng + 1 < N) C[(size_t)mg * N + ng + 1] = (v1 + bias[ng + 1]) * 100.0f;
        }
    }
}

// ---------------- DMP Euler integration --------------------------------------
__global__ __launch_bounds__(256)
void dmp_kernel(const float* __restrict__ input, float* __restrict__ out)
{
    __shared__ float xs[NSTEP];
    __shared__ float coef[NSTEP][NBAS];

    const int tid = threadIdx.x;
    if (tid == 0) {
        float x = 1.0f;
        for (int i = 0; i < NSTEP; i++) { x = x - x * 0.01f; xs[i] = x; }
    }
    __syncthreads();
    if (tid < NSTEP) {
        float x = xs[tid];
        float p[NBAS];
        float s = 0.0f;
#pragma unroll
        for (int n = 0; n < NBAS; n++) {
            double cd = exp(-0.25 * (double)n);
            float Cn = (float)cd;
            float Hn = (float)(11.180339887498949 / cd);
            float d = x - Cn;
            p[n] = __expf(-Hn * d * d);
            s += p[n];
        }
        float inv = x / s;
#pragma unroll
        for (int n = 0; n < NBAS; n++) coef[tid][n] = p[n] * inv;
    }
    __syncthreads();

    int r = blockIdx.x * blockDim.x + tid;
    if (r >= BATCH * NDIM) return;
    int b = r / NDIM;
    int d = r - b * NDIM;

    const float* prm = g_par + (size_t)b * OUTP;
    float goal = prm[d];
    float w[NBAS];
#pragma unroll
    for (int n = 0; n < NBAS; n++) w[n] = prm[NDIM + d * NBAS + n];

    float y = input[(size_t)b * D_INPUT + 7 + d];
    float z = input[(size_t)b * D_INPUT + 22 + d];
    float scale = goal - y;
    float prev = y;
    float* o = out + (size_t)r * 10;

#pragma unroll 1
    for (int kk = 0; kk < 10; kk++) {
#pragma unroll
        for (int i = 0; i < 10; i++) {
            int t = kk * 10 + i;
            float fx = scale * (w[0] * coef[t][0] + w[1] * coef[t][1] +
                                w[2] * coef[t][2] + w[3] * coef[t][3] +
                                w[4] * coef[t][4]);
            float dz = 25.0f * (6.25f * (goal - y) - z) + fx;
            y = y + z * 0.01f;
            z = z + dz * 0.01f;
        }
        o[kk] = y - prev;
        prev = y;
    }
}

// ---------------- launch ------------------------------------------------------
extern "C" void kernel_launch(void* const* d_in, const int* in_sizes, int n_in,
                              void* d_out, int out_size)
{
    const float* input = (const float*)d_in[0];
    const float* W0 = (const float*)d_in[1];
    const float* b0 = (const float*)d_in[2];
    const float* W1 = (const float*)d_in[3];
    const float* b1 = (const float*)d_in[4];
    const float* Wl = (const float*)d_in[5];
    const float* bl = (const float*)d_in[6];
    float* out = (float*)d_out;

    static __nv_bfloat16 *in3, *w0_3, *w1_3, *h1_3;
    static float *h2, *par;
    static bool init_done = false;
    if (!init_done) {
        cudaGetSymbolAddress((void**)&in3, g_in3);
        cudaGetSymbolAddress((void**)&w0_3, g_w0_3);
        cudaGetSymbolAddress((void**)&w1_3, g_w1_3);
        cudaGetSymbolAddress((void**)&h1_3, g_h1_3);
        cudaGetSymbolAddress((void**)&h2, g_h2);
        cudaGetSymbolAddress((void**)&par, g_par);
        cudaFuncSetAttribute(gemm_mma<0>, cudaFuncAttributeMaxDynamicSharedMemorySize, MMA_SMEM);
        cudaFuncSetAttribute(gemm_mma<1>, cudaFuncAttributeMaxDynamicSharedMemorySize, MMA_SMEM);
        init_done = true;
    }

    dim3 blk(256);
    // fp32 -> 3K split-bf16 layouts
    split3<0><<<(BATCH * D_INPUT / 4 + 255) / 256, blk>>>(input, in3, D_INPUT, BATCH * D_INPUT / 4);
    split3<1><<<(HIDDEN * D_INPUT / 4 + 255) / 256, blk>>>(W0, w0_3, D_INPUT, HIDDEN * D_INPUT / 4);
    split3<1><<<(HIDDEN * HIDDEN / 4 + 255) / 256, blk>>>(W1, w1_3, HIDDEN, HIDDEN * HIDDEN / 4);

    // layer 0: tanh(input @ W0^T + b0) -> h1 in [hi|hi|lo] layout (K2 = 384)
    gemm_mma<0><<<dim3(HIDDEN / 128, BATCH / 256), dim3(512), MMA_SMEM>>>(
        in3, w0_3, b0, nullptr, h1_3, HIDDEN, 3 * D_INPUT);
    // layer 1: tanh(h1 @ W1^T + b1) -> fp32 h2 (K2 = 6144, dominant)
    gemm_mma<1><<<dim3(HIDDEN / 128, BATCH / 256), dim3(512), MMA_SMEM>>>(
        h1_3, w1_3, b1, h2, nullptr, HIDDEN, 3 * HIDDEN);
    // final: (h2 @ Wl^T + bl) * 100
    gemm64<<<dim3(1, BATCH / 64), blk>>>(h2, Wl, bl, par, OUTP, HIDDEN);
    // DMP integration + subsample-diff
    dmp_kernel<<<(BATCH * NDIM + 255) / 256, blk>>>(input, out);
}